// round 13
// baseline (speedup 1.0000x reference)
#include <cuda_runtime.h>
#include <cuda_pipeline.h>
#include <math.h>

#define D_ 1024
#define H_ 8
#define F_ 4096
#define SR 4         // rows per score stage
#define SCHUNK 256   // floats per row-chunk per stage (1KB)
#define NSTG 6       // pipeline stages per warp
#define STG_FLOATS (SR * SCHUNK)   // 4KB per stage
#define KMAX 2048    // per-(b,h) list stride (k <= 1843)

// Scratch
__device__ unsigned long long g_keys[8 * 4096 * 8];
__device__ float g_mask[64 * 4096];     // [bh][f]
__device__ int   g_list[64 * KMAX];     // compacted kept f-indices per bh
__device__ int   g_cnt[64];

__device__ __forceinline__ unsigned int f2ord(float f) {
    unsigned int u = __float_as_uint(f);
    return (u & 0x80000000u) ? ~u : (u | 0x80000000u);
}
__device__ __forceinline__ unsigned long long pack2(float lo, float hi) {
    unsigned long long p;
    asm("mov.b64 %0, {%1, %2};" : "=l"(p) : "f"(lo), "f"(hi));
    return p;
}
__device__ __forceinline__ void unpack2(unsigned long long p, float& lo, float& hi) {
    asm("mov.b64 {%0, %1}, %2;" : "=f"(lo), "=f"(hi) : "l"(p));
}
__device__ __forceinline__ unsigned long long shfl_xor64(unsigned long long v, int off) {
    unsigned int lo = __shfl_xor_sync(0xffffffffu, (unsigned int)v, off);
    unsigned int hi = __shfl_xor_sync(0xffffffffu, (unsigned int)(v >> 32), off);
    return ((unsigned long long)hi << 32) | lo;
}
#define FMA2(acc, a, b) \
    asm("fma.rn.f32x2 %0, %1, %2, %0;" : "+l"(acc) : "l"(a), "l"(b))
#define ADD2(acc, a) \
    asm("add.rn.f32x2 %0, %0, %1;" : "+l"(acc) : "l"(a))

__device__ __forceinline__ void issue_stage(
    const float* __restrict__ x, float* dst,
    int batch, int c, int lane)
{
    const float* src = x + (size_t)batch * SR * D_ + c * SCHUNK;
#pragma unroll
    for (int r = 0; r < SR; r++)
#pragma unroll
        for (int q = 0; q < 2; q++)
            __pipeline_memcpy_async(dst + r * SCHUNK + (lane + 32 * q) * 4,
                                    src + (size_t)r * D_ + (lane + 32 * q) * 4, 16);
}

// ---------------------------------------------------------------------------
// Kernel 1: warp-private cp.async 6-stage pipelined score + xout zero-fill
// (zero writes drain through L2 nearly for free; filter never writes zeros).
// ---------------------------------------------------------------------------
__global__ void __launch_bounds__(256, 1) score_kernel(
    const float* __restrict__ x,
    const float* __restrict__ W,      // [D, H]
    const float* __restrict__ bias,   // [H]
    float* __restrict__ xout,         // zero-filled here
    int nrows)
{
    extern __shared__ float smem[];
    float* Wt  = smem;                          // 32KB
    float* stg = smem + H_ * D_;                // 8 warps * NSTG * 4KB

    const int tid  = threadIdx.x;
    const int warp = tid >> 5;
    const int lane = tid & 31;
    const int bid  = blockIdx.x;
    const int grid = gridDim.x;

    for (int i = tid; i < D_ * H_; i += 256) {
        int d = i >> 3, h = i & 7;
        Wt[h * D_ + d] = W[i];
    }
    __syncthreads();

    const int j0 = __brev((unsigned)lane) >> 27;
    const int h0 = j0 & 7;
    const int rA = j0 >> 3;
    const float bias_h = bias[h0];

    const int nbatch = nrows / SR;
    const int gw = bid * 8 + warp;
    const int nwarps = grid * 8;
    const int my_n = (nbatch > gw) ? ((nbatch - gw + nwarps - 1) / nwarps) : 0;
    const int total_m = my_n * 4;
    if (total_m == 0) return;

    float* buf = stg + warp * NSTG * STG_FLOATS;
    const unsigned long long ABS2 = 0x7FFFFFFF7FFFFFFFull;
    const float4 z4 = make_float4(0.f, 0.f, 0.f, 0.f);

#pragma unroll
    for (int i = 0; i < NSTG - 1; i++) {
        if (i < total_m)
            issue_stage(x, buf + (i % NSTG) * STG_FLOATS,
                        gw + (i >> 2) * nwarps, i & 3, lane);
        __pipeline_commit();
    }

    unsigned long long acc[32];

    for (int m = 0; m < total_m; m++) {
        const int c = m & 3;
        const int batch = gw + (m >> 2) * nwarps;

        {
            const int mi = m + NSTG - 1;
            if (mi < total_m)
                issue_stage(x, buf + (mi % NSTG) * STG_FLOATS,
                            gw + (mi >> 2) * nwarps, mi & 3, lane);
            __pipeline_commit();
        }
        __pipeline_wait_prior(NSTG - 1);

        if (c == 0) {
#pragma unroll
            for (int j = 0; j < 32; j++) acc[j] = 0ull;
        }

        const float4* bp = (const float4*)(buf + (m % NSTG) * STG_FLOATS);
#pragma unroll
        for (int j2 = 0; j2 < 2; j2++) {
            const int d4l = lane + 32 * j2;
            unsigned long long axy[SR], azw[SR];
#pragma unroll
            for (int r = 0; r < SR; r++) {
                float4 v = bp[r * (SCHUNK / 4) + d4l];
                axy[r] = pack2(v.x, v.y) & ABS2;
                azw[r] = pack2(v.z, v.w) & ABS2;
            }
            const int dg = c * SCHUNK + 4 * d4l;
#pragma unroll
            for (int h = 0; h < H_; h++) {
                const ulonglong2 wv = *(const ulonglong2*)&Wt[h * D_ + dg];
#pragma unroll
                for (int r = 0; r < SR; r++) {
                    FMA2(acc[r * 8 + h], axy[r], wv.x);
                    FMA2(acc[r * 8 + h], azw[r], wv.y);
                }
            }
        }

        {   // mirror zero-fill of xout
            float* zo = xout + (size_t)batch * SR * D_ + c * SCHUNK;
#pragma unroll
            for (int r = 0; r < SR; r++)
#pragma unroll
                for (int q = 0; q < 2; q++)
                    __stcs((float4*)(zo + (size_t)r * D_ + (lane + 32 * q) * 4), z4);
        }

        if (c == 3) {
            int n = 32;
#pragma unroll
            for (int off = 16; off >= 1; off >>= 1) {
#pragma unroll
                for (int i = 0; i < 16; i++) {
                    if (i < n / 2) {
                        unsigned long long xx = acc[2 * i], yy = acc[2 * i + 1];
                        unsigned long long t = (lane & off) ? xx : yy;
                        t = shfl_xor64(t, off);
                        unsigned long long keep = (lane & off) ? yy : xx;
                        ADD2(keep, t);
                        acc[i] = keep;
                    }
                }
                n >>= 1;
            }
            const int row = batch * SR + rA;
            float lo, hi;
            unpack2(acc[0], lo, hi);
            float s = lo + hi + bias_h;
            const int b = row / F_;
            const int f = row - b * F_;
            const unsigned int finv = 0xFFFFFFFFu - (unsigned int)f;
            g_keys[(size_t)row * H_ + h0] =
                ((unsigned long long)f2ord(s) << 32) | (unsigned long long)finv;
        }
    }
}

// ---------------------------------------------------------------------------
// Kernel 2: per (b,h) exact radix-select + mask scratch + COMPACTED kept-f
// list (smem-atomic slot assignment; order irrelevant, copies are disjoint).
// ---------------------------------------------------------------------------
__global__ void __launch_bounds__(1024) topk_kernel(
    const float* __restrict__ sparsity_offset)
{
    __shared__ unsigned long long s[F_];   // 32 KB
    __shared__ int hist[4][256];
    __shared__ int sh_bin, sh_need, sh_cnt;

    const int bh = blockIdx.x;
    const int b  = bh >> 3;
    const int h  = bh & (H_ - 1);
    const int t  = threadIdx.x;
    const int lane = t & 31;
    const int wg4 = (t >> 5) & 3;

#pragma unroll
    for (int j = 0; j < 4; j++) {
        int i = t + j * 1024;
        s[i] = g_keys[((size_t)b * F_ + i) * H_ + h];
    }

    if (t == 0) {
        double off = (double)sparsity_offset[h];
        double sp  = 1.0 / (1.0 + exp(-off)) * 0.3 + 0.15;
        int k = (int)((double)F_ * sp);     // trunc, matches numpy int()
        if (k < 1)  k = 1;
        if (k > F_) k = F_;
        sh_need = k;
        sh_cnt = 0;
    }
    __syncthreads();

    unsigned long long prefix = 0ull, pmask = 0ull;

    for (int shift = 56; shift >= 0; shift -= 8) {
        if (t < 256) { hist[0][t] = 0; hist[1][t] = 0; hist[2][t] = 0; hist[3][t] = 0; }
        __syncthreads();
#pragma unroll
        for (int j = 0; j < 4; j++) {
            unsigned long long key = s[t + j * 1024];
            if ((key & pmask) == prefix)
                atomicAdd(&hist[wg4][(int)((key >> shift) & 255ull)], 1);
        }
        __syncthreads();

        if (t < 32) {
            int c[8], lsum = 0;
#pragma unroll
            for (int q = 0; q < 8; q++) {
                int bin = lane * 8 + q;
                c[q] = hist[0][bin] + hist[1][bin] + hist[2][bin] + hist[3][bin];
                lsum += c[q];
            }
            int ssum = lsum;
#pragma unroll
            for (int off = 1; off < 32; off <<= 1) {
                int o = __shfl_down_sync(0xffffffffu, ssum, off);
                if (lane + off < 32) ssum += o;
            }
            int above = ssum - lsum;
            int need = sh_need;
            int cum = above;
#pragma unroll
            for (int q = 7; q >= 0; q--) {
                int bin = lane * 8 + q;
                if (cum < need && need <= cum + c[q]) {
                    sh_bin = bin;
                    sh_need = need - cum;
                }
                cum += c[q];
            }
        }
        __syncthreads();
        prefix |= ((unsigned long long)sh_bin) << shift;
        pmask  |= (255ull << shift);
        __syncthreads();
    }

    // mask scratch + compact list
#pragma unroll
    for (int j = 0; j < 4; j++) {
        int i = t + j * 1024;
        bool kept = (s[i] >= prefix);
        g_mask[(size_t)bh * F_ + i] = kept ? 1.0f : 0.0f;
        if (kept) {
            int p = atomicAdd(&sh_cnt, 1);
            g_list[bh * KMAX + p] = i;
        }
    }
    __syncthreads();
    if (t == 0) g_cnt[bh] = sh_cnt;
}

// ---------------------------------------------------------------------------
// Kernel 3: branch-free copy of kept head-slices. One warp = one 512B slice:
// unconditional LDG.128 + STG.128 per lane, maximal MLP across warps.
// ---------------------------------------------------------------------------
__global__ void __launch_bounds__(256) copy_kernel(
    const float* __restrict__ x,
    float* __restrict__ xout)
{
    const int gw = blockIdx.x * 8 + (threadIdx.x >> 5);
    const int lane = threadIdx.x & 31;
    const int bh = gw >> 11;            // KMAX = 2048
    const int i  = gw & (KMAX - 1);
    if (i >= g_cnt[bh]) return;
    const int f = g_list[bh * KMAX + i];
    const int b = bh >> 3;
    const int h = bh & 7;
    const size_t base = ((size_t)(b * F_ + f)) * D_ + h * 128 + lane * 4;
    float4 v = *(const float4*)(x + base);
    *(float4*)(xout + base) = v;
}

// ---------------------------------------------------------------------------
// Kernel 4: mask region of d_out, coalesced both sides via smem transpose.
// ---------------------------------------------------------------------------
__global__ void __launch_bounds__(256) mask_kernel(
    float* __restrict__ mask_out)
{
    __shared__ float m[32][H_];
    const int tile0 = blockIdx.x * 32;
    const int b = tile0 >> 12;
    const int f0 = tile0 & (F_ - 1);
    const int t = threadIdx.x;

    {
        const int h = t >> 5;
        const int f = f0 + (t & 31);
        m[t & 31][h] = g_mask[((size_t)(b * H_ + h)) * F_ + f];
    }
    __syncthreads();
    mask_out[(size_t)tile0 * H_ + t] = m[t >> 3][t & 7];
}

// ---------------------------------------------------------------------------
extern "C" void kernel_launch(void* const* d_in, const int* in_sizes, int n_in,
                              void* d_out, int out_size)
{
    const float* x    = (const float*)d_in[0];  // (B,F,D)
    const float* W    = (const float*)d_in[1];  // (D,H)
    const float* bias = (const float*)d_in[2];  // (H)
    const float* soff = (const float*)d_in[3];  // (H)

    const int nrows = in_sizes[0] / D_;         // B*F
    const int B = nrows / F_;

    float* xout = (float*)d_out;
    float* mask_out = nullptr;
    long long need = (long long)nrows * D_ + (long long)nrows * H_;
    if ((long long)out_size >= need)
        mask_out = (float*)d_out + (size_t)nrows * D_;

    const int smem_bytes = (H_ * D_ + 8 * NSTG * STG_FLOATS) * sizeof(float); // 224KB
    static int attr_set = 0;
    if (!attr_set) {
        cudaFuncSetAttribute(score_kernel,
                             cudaFuncAttributeMaxDynamicSharedMemorySize, smem_bytes);
        attr_set = 1;
    }

    // 1) scores -> keys + zero-fill xout
    score_kernel<<<148, 256, smem_bytes>>>(x, W, bias, xout, nrows);
    // 2) exact top-k + mask scratch + compact lists
    topk_kernel<<<B * H_, 1024>>>(soff);
    // 3) branch-free copy of kept slices
    copy_kernel<<<(B * H_ * KMAX) / 8, 256>>>(x, xout);
    // 4) mask region
    if (mask_out) mask_kernel<<<nrows / 32, 256>>>(mask_out);
}

// round 14
// speedup vs baseline: 1.0612x; 1.0612x over previous
#include <cuda_runtime.h>
#include <cuda_pipeline.h>
#include <math.h>

#define D_ 1024
#define H_ 8
#define F_ 4096
#define SR 4         // rows per score stage
#define SCHUNK 256   // floats per row-chunk per stage (1KB)
#define NSTG 6       // pipeline stages per warp
#define STG_FLOATS (SR * SCHUNK)   // 4KB per stage
#define KMAX 2048    // per-(b,h) list stride (k <= 1843)

// Scratch
__device__ unsigned long long g_keys[8 * 4096 * 8];
__device__ float g_mask[64 * 4096];     // [bh][f]
__device__ int   g_list[64 * KMAX];     // compacted kept f-indices, -1 padded

__device__ __forceinline__ unsigned int f2ord(float f) {
    unsigned int u = __float_as_uint(f);
    return (u & 0x80000000u) ? ~u : (u | 0x80000000u);
}
__device__ __forceinline__ unsigned long long pack2(float lo, float hi) {
    unsigned long long p;
    asm("mov.b64 %0, {%1, %2};" : "=l"(p) : "f"(lo), "f"(hi));
    return p;
}
__device__ __forceinline__ void unpack2(unsigned long long p, float& lo, float& hi) {
    asm("mov.b64 {%0, %1}, %2;" : "=f"(lo), "=f"(hi) : "l"(p));
}
__device__ __forceinline__ unsigned long long shfl_xor64(unsigned long long v, int off) {
    unsigned int lo = __shfl_xor_sync(0xffffffffu, (unsigned int)v, off);
    unsigned int hi = __shfl_xor_sync(0xffffffffu, (unsigned int)(v >> 32), off);
    return ((unsigned long long)hi << 32) | lo;
}
#define FMA2(acc, a, b) \
    asm("fma.rn.f32x2 %0, %1, %2, %0;" : "+l"(acc) : "l"(a), "l"(b))
#define ADD2(acc, a) \
    asm("add.rn.f32x2 %0, %0, %1;" : "+l"(acc) : "l"(a))

__device__ __forceinline__ void issue_stage(
    const float* __restrict__ x, float* dst,
    int batch, int c, int lane)
{
    const float* src = x + (size_t)batch * SR * D_ + c * SCHUNK;
#pragma unroll
    for (int r = 0; r < SR; r++)
#pragma unroll
        for (int q = 0; q < 2; q++)
            __pipeline_memcpy_async(dst + r * SCHUNK + (lane + 32 * q) * 4,
                                    src + (size_t)r * D_ + (lane + 32 * q) * 4, 16);
}

// ---------------------------------------------------------------------------
// Kernel 1: warp-private cp.async 6-stage pipelined score + xout zero-fill.
// ---------------------------------------------------------------------------
__global__ void __launch_bounds__(256, 1) score_kernel(
    const float* __restrict__ x,
    const float* __restrict__ W,      // [D, H]
    const float* __restrict__ bias,   // [H]
    float* __restrict__ xout,         // zero-filled here
    int nrows)
{
    extern __shared__ float smem[];
    float* Wt  = smem;                          // 32KB
    float* stg = smem + H_ * D_;                // 8 warps * NSTG * 4KB

    const int tid  = threadIdx.x;
    const int warp = tid >> 5;
    const int lane = tid & 31;
    const int bid  = blockIdx.x;
    const int grid = gridDim.x;

    for (int i = tid; i < D_ * H_; i += 256) {
        int d = i >> 3, h = i & 7;
        Wt[h * D_ + d] = W[i];
    }
    __syncthreads();

    const int j0 = __brev((unsigned)lane) >> 27;
    const int h0 = j0 & 7;
    const int rA = j0 >> 3;
    const float bias_h = bias[h0];

    const int nbatch = nrows / SR;
    const int gw = bid * 8 + warp;
    const int nwarps = grid * 8;
    const int my_n = (nbatch > gw) ? ((nbatch - gw + nwarps - 1) / nwarps) : 0;
    const int total_m = my_n * 4;
    if (total_m == 0) return;

    float* buf = stg + warp * NSTG * STG_FLOATS;
    const unsigned long long ABS2 = 0x7FFFFFFF7FFFFFFFull;
    const float4 z4 = make_float4(0.f, 0.f, 0.f, 0.f);

#pragma unroll
    for (int i = 0; i < NSTG - 1; i++) {
        if (i < total_m)
            issue_stage(x, buf + (i % NSTG) * STG_FLOATS,
                        gw + (i >> 2) * nwarps, i & 3, lane);
        __pipeline_commit();
    }

    unsigned long long acc[32];

    for (int m = 0; m < total_m; m++) {
        const int c = m & 3;
        const int batch = gw + (m >> 2) * nwarps;

        {
            const int mi = m + NSTG - 1;
            if (mi < total_m)
                issue_stage(x, buf + (mi % NSTG) * STG_FLOATS,
                            gw + (mi >> 2) * nwarps, mi & 3, lane);
            __pipeline_commit();
        }
        __pipeline_wait_prior(NSTG - 1);

        if (c == 0) {
#pragma unroll
            for (int j = 0; j < 32; j++) acc[j] = 0ull;
        }

        const float4* bp = (const float4*)(buf + (m % NSTG) * STG_FLOATS);
#pragma unroll
        for (int j2 = 0; j2 < 2; j2++) {
            const int d4l = lane + 32 * j2;
            unsigned long long axy[SR], azw[SR];
#pragma unroll
            for (int r = 0; r < SR; r++) {
                float4 v = bp[r * (SCHUNK / 4) + d4l];
                axy[r] = pack2(v.x, v.y) & ABS2;
                azw[r] = pack2(v.z, v.w) & ABS2;
            }
            const int dg = c * SCHUNK + 4 * d4l;
#pragma unroll
            for (int h = 0; h < H_; h++) {
                const ulonglong2 wv = *(const ulonglong2*)&Wt[h * D_ + dg];
#pragma unroll
                for (int r = 0; r < SR; r++) {
                    FMA2(acc[r * 8 + h], axy[r], wv.x);
                    FMA2(acc[r * 8 + h], azw[r], wv.y);
                }
            }
        }

        {   // mirror zero-fill of xout
            float* zo = xout + (size_t)batch * SR * D_ + c * SCHUNK;
#pragma unroll
            for (int r = 0; r < SR; r++)
#pragma unroll
                for (int q = 0; q < 2; q++)
                    __stcs((float4*)(zo + (size_t)r * D_ + (lane + 32 * q) * 4), z4);
        }

        if (c == 3) {
            int n = 32;
#pragma unroll
            for (int off = 16; off >= 1; off >>= 1) {
#pragma unroll
                for (int i = 0; i < 16; i++) {
                    if (i < n / 2) {
                        unsigned long long xx = acc[2 * i], yy = acc[2 * i + 1];
                        unsigned long long t = (lane & off) ? xx : yy;
                        t = shfl_xor64(t, off);
                        unsigned long long keep = (lane & off) ? yy : xx;
                        ADD2(keep, t);
                        acc[i] = keep;
                    }
                }
                n >>= 1;
            }
            const int row = batch * SR + rA;
            float lo, hi;
            unpack2(acc[0], lo, hi);
            float s = lo + hi + bias_h;
            const int b = row / F_;
            const int f = row - b * F_;
            const unsigned int finv = 0xFFFFFFFFu - (unsigned int)f;
            g_keys[(size_t)row * H_ + h0] =
                ((unsigned long long)f2ord(s) << 32) | (unsigned long long)finv;
        }
    }
}

// ---------------------------------------------------------------------------
// Kernel 2: per (b,h) exact radix-select + mask scratch + compacted,
// SENTINEL-PADDED kept-f list (copy kernel needs no count load).
// ---------------------------------------------------------------------------
__global__ void __launch_bounds__(1024) topk_kernel(
    const float* __restrict__ sparsity_offset)
{
    __shared__ unsigned long long s[F_];   // 32 KB
    __shared__ int hist[4][256];
    __shared__ int sh_bin, sh_need, sh_cnt;

    const int bh = blockIdx.x;
    const int b  = bh >> 3;
    const int h  = bh & (H_ - 1);
    const int t  = threadIdx.x;
    const int lane = t & 31;
    const int wg4 = (t >> 5) & 3;

#pragma unroll
    for (int j = 0; j < 4; j++) {
        int i = t + j * 1024;
        s[i] = g_keys[((size_t)b * F_ + i) * H_ + h];
    }

    if (t == 0) {
        double off = (double)sparsity_offset[h];
        double sp  = 1.0 / (1.0 + exp(-off)) * 0.3 + 0.15;
        int k = (int)((double)F_ * sp);     // trunc, matches numpy int()
        if (k < 1)  k = 1;
        if (k > F_) k = F_;
        sh_need = k;
        sh_cnt = 0;
    }
    __syncthreads();

    unsigned long long prefix = 0ull, pmask = 0ull;

    for (int shift = 56; shift >= 0; shift -= 8) {
        if (t < 256) { hist[0][t] = 0; hist[1][t] = 0; hist[2][t] = 0; hist[3][t] = 0; }
        __syncthreads();
#pragma unroll
        for (int j = 0; j < 4; j++) {
            unsigned long long key = s[t + j * 1024];
            if ((key & pmask) == prefix)
                atomicAdd(&hist[wg4][(int)((key >> shift) & 255ull)], 1);
        }
        __syncthreads();

        if (t < 32) {
            int c[8], lsum = 0;
#pragma unroll
            for (int q = 0; q < 8; q++) {
                int bin = lane * 8 + q;
                c[q] = hist[0][bin] + hist[1][bin] + hist[2][bin] + hist[3][bin];
                lsum += c[q];
            }
            int ssum = lsum;
#pragma unroll
            for (int off = 1; off < 32; off <<= 1) {
                int o = __shfl_down_sync(0xffffffffu, ssum, off);
                if (lane + off < 32) ssum += o;
            }
            int above = ssum - lsum;
            int need = sh_need;
            int cum = above;
#pragma unroll
            for (int q = 7; q >= 0; q--) {
                int bin = lane * 8 + q;
                if (cum < need && need <= cum + c[q]) {
                    sh_bin = bin;
                    sh_need = need - cum;
                }
                cum += c[q];
            }
        }
        __syncthreads();
        prefix |= ((unsigned long long)sh_bin) << shift;
        pmask  |= (255ull << shift);
        __syncthreads();
    }

    // mask scratch + compact list
#pragma unroll
    for (int j = 0; j < 4; j++) {
        int i = t + j * 1024;
        bool kept = (s[i] >= prefix);
        g_mask[(size_t)bh * F_ + i] = kept ? 1.0f : 0.0f;
        if (kept) {
            int p = atomicAdd(&sh_cnt, 1);
            g_list[bh * KMAX + p] = i;
        }
    }
    __syncthreads();
    // sentinel padding
    for (int i = sh_cnt + t; i < KMAX; i += 1024)
        g_list[bh * KMAX + i] = -1;
}

// ---------------------------------------------------------------------------
// Kernel 3: copy + mask output, one launch.
// Copy blocks: 32 slices of one (b,h) per block; list entries loaded once
// coalesced into smem; each warp does 4 slices with batched LDG then STG.
// Mask blocks: 128-row transpose tiles.
// ---------------------------------------------------------------------------
__global__ void __launch_bounds__(256) copy_mask_kernel(
    const float* __restrict__ x,
    float* __restrict__ xout,
    float* __restrict__ mask_out,     // may be null
    int ncopy)                        // B*H*(KMAX/32) copy blocks
{
    const int t = threadIdx.x;

    if ((int)blockIdx.x < ncopy) {
        __shared__ int fl[32];
        const int bh = blockIdx.x >> 6;          // KMAX/32 = 64 chunks per bh
        const int i0 = (blockIdx.x & 63) * 32;
        if (t < 32) fl[t] = g_list[bh * KMAX + i0 + t];
        __syncthreads();

        const int warp = t >> 5;
        const int lane = t & 31;
        const int b = bh >> 3;
        const int h = bh & 7;
        const size_t hoff = (size_t)h * 128 + lane * 4;

        int fs[4];
#pragma unroll
        for (int s = 0; s < 4; s++) fs[s] = fl[s * 8 + warp];

        float4 v[4];
#pragma unroll
        for (int s = 0; s < 4; s++)              // batched independent loads
            if (fs[s] >= 0)
                v[s] = *(const float4*)(x + ((size_t)(b * F_ + fs[s])) * D_ + hoff);
#pragma unroll
        for (int s = 0; s < 4; s++)
            if (fs[s] >= 0)
                __stcs((float4*)(xout + ((size_t)(b * F_ + fs[s])) * D_ + hoff), v[s]);
    } else {
        // mask tile: 128 rows x 8 heads
        __shared__ float mm[128 * H_];
        const int tile0 = ((int)blockIdx.x - ncopy) * 128;   // row base
        const int b = tile0 >> 12;                // F_ = 4096
        const int f0 = tile0 & (F_ - 1);
#pragma unroll
        for (int j = 0; j < 4; j++) {
            int idx = t + j * 256;                // 0..1023
            int h = idx >> 7;                     // 0..7
            int fi = idx & 127;
            mm[fi * H_ + h] = g_mask[((size_t)(b * H_ + h)) * F_ + f0 + fi];
        }
        __syncthreads();
        if (mask_out) {
            float4* mo = (float4*)(mask_out + (size_t)tile0 * H_);
            const float4* ms = (const float4*)mm;
            mo[t] = ms[t];                        // 4KB coalesced
        }
    }
}

// ---------------------------------------------------------------------------
extern "C" void kernel_launch(void* const* d_in, const int* in_sizes, int n_in,
                              void* d_out, int out_size)
{
    const float* x    = (const float*)d_in[0];  // (B,F,D)
    const float* W    = (const float*)d_in[1];  // (D,H)
    const float* bias = (const float*)d_in[2];  // (H)
    const float* soff = (const float*)d_in[3];  // (H)

    const int nrows = in_sizes[0] / D_;         // B*F
    const int B = nrows / F_;

    float* xout = (float*)d_out;
    float* mask_out = nullptr;
    long long need = (long long)nrows * D_ + (long long)nrows * H_;
    if ((long long)out_size >= need)
        mask_out = (float*)d_out + (size_t)nrows * D_;

    const int smem_bytes = (H_ * D_ + 8 * NSTG * STG_FLOATS) * sizeof(float); // 224KB
    static int attr_set = 0;
    if (!attr_set) {
        cudaFuncSetAttribute(score_kernel,
                             cudaFuncAttributeMaxDynamicSharedMemorySize, smem_bytes);
        attr_set = 1;
    }

    // 1) scores -> keys + zero-fill xout
    score_kernel<<<148, 256, smem_bytes>>>(x, W, bias, xout, nrows);
    // 2) exact top-k + mask scratch + sentinel-padded compact lists
    topk_kernel<<<B * H_, 1024>>>(soff);
    // 3) copy kept slices + mask region, one launch
    const int ncopy = B * H_ * (KMAX / 32);
    const int nmask = nrows / 128;
    copy_mask_kernel<<<ncopy + nmask, 256>>>(x, xout, mask_out, ncopy);
}

// round 15
// speedup vs baseline: 1.1541x; 1.0875x over previous
#include <cuda_runtime.h>
#include <cuda_pipeline.h>
#include <math.h>

#define D_ 1024
#define H_ 8
#define F_ 4096
#define TILE_ 32     // rows per filter block
#define SR 4         // rows per score stage
#define SCHUNK 256   // floats per row-chunk per stage (1KB)
#define NSTG 6       // pipeline stages per warp
#define STG_FLOATS (SR * SCHUNK)   // 4KB per stage

// Scratch
__device__ unsigned long long g_keys[8 * 4096 * 8];   // [b][f][h]
__device__ float g_mask[64 * 4096];                   // [bh][f]

__device__ __forceinline__ unsigned int f2ord(float f) {
    unsigned int u = __float_as_uint(f);
    return (u & 0x80000000u) ? ~u : (u | 0x80000000u);
}
__device__ __forceinline__ unsigned long long pack2(float lo, float hi) {
    unsigned long long p;
    asm("mov.b64 %0, {%1, %2};" : "=l"(p) : "f"(lo), "f"(hi));
    return p;
}
__device__ __forceinline__ void unpack2(unsigned long long p, float& lo, float& hi) {
    asm("mov.b64 {%0, %1}, %2;" : "=f"(lo), "=f"(hi) : "l"(p));
}
__device__ __forceinline__ unsigned long long shfl_xor64(unsigned long long v, int off) {
    unsigned int lo = __shfl_xor_sync(0xffffffffu, (unsigned int)v, off);
    unsigned int hi = __shfl_xor_sync(0xffffffffu, (unsigned int)(v >> 32), off);
    return ((unsigned long long)hi << 32) | lo;
}
#define FMA2(acc, a, b) \
    asm("fma.rn.f32x2 %0, %1, %2, %0;" : "+l"(acc) : "l"(a), "l"(b))
#define ADD2(acc, a) \
    asm("add.rn.f32x2 %0, %0, %1;" : "+l"(acc) : "l"(a))

__device__ __forceinline__ void issue_stage(
    const float* __restrict__ x, float* dst,
    int batch, int c, int lane)
{
    const float* src = x + (size_t)batch * SR * D_ + c * SCHUNK;
#pragma unroll
    for (int r = 0; r < SR; r++)
#pragma unroll
        for (int q = 0; q < 2; q++)
            __pipeline_memcpy_async(dst + r * SCHUNK + (lane + 32 * q) * 4,
                                    src + (size_t)r * D_ + (lane + 32 * q) * 4, 16);
}

// ---------------------------------------------------------------------------
// Kernel 1: warp-private cp.async 6-stage pipelined score (round-11 exact
// structure; measured 28.7us). No zero-fill -- dense filter writes once.
// ---------------------------------------------------------------------------
__global__ void __launch_bounds__(256, 1) score_kernel(
    const float* __restrict__ x,
    const float* __restrict__ W,      // [D, H]
    const float* __restrict__ bias,   // [H]
    int nrows)
{
    extern __shared__ float smem[];
    float* Wt  = smem;                          // 32KB
    float* stg = smem + H_ * D_;                // 8 warps * NSTG * 4KB

    const int tid  = threadIdx.x;
    const int warp = tid >> 5;
    const int lane = tid & 31;
    const int bid  = blockIdx.x;
    const int grid = gridDim.x;

    for (int i = tid; i < D_ * H_; i += 256) {
        int d = i >> 3, h = i & 7;
        Wt[h * D_ + d] = W[i];
    }
    __syncthreads();

    const int j0 = __brev((unsigned)lane) >> 27;
    const int h0 = j0 & 7;
    const int rA = j0 >> 3;
    const float bias_h = bias[h0];

    const int nbatch = nrows / SR;
    const int gw = bid * 8 + warp;
    const int nwarps = grid * 8;
    const int my_n = (nbatch > gw) ? ((nbatch - gw + nwarps - 1) / nwarps) : 0;
    const int total_m = my_n * 4;
    if (total_m == 0) return;

    float* buf = stg + warp * NSTG * STG_FLOATS;
    const unsigned long long ABS2 = 0x7FFFFFFF7FFFFFFFull;

#pragma unroll
    for (int i = 0; i < NSTG - 1; i++) {
        if (i < total_m)
            issue_stage(x, buf + (i % NSTG) * STG_FLOATS,
                        gw + (i >> 2) * nwarps, i & 3, lane);
        __pipeline_commit();
    }

    unsigned long long acc[32];

    for (int m = 0; m < total_m; m++) {
        const int c = m & 3;
        const int batch = gw + (m >> 2) * nwarps;

        {
            const int mi = m + NSTG - 1;
            if (mi < total_m)
                issue_stage(x, buf + (mi % NSTG) * STG_FLOATS,
                            gw + (mi >> 2) * nwarps, mi & 3, lane);
            __pipeline_commit();
        }
        __pipeline_wait_prior(NSTG - 1);

        if (c == 0) {
#pragma unroll
            for (int j = 0; j < 32; j++) acc[j] = 0ull;
        }

        const float4* bp = (const float4*)(buf + (m % NSTG) * STG_FLOATS);
#pragma unroll
        for (int j2 = 0; j2 < 2; j2++) {
            const int d4l = lane + 32 * j2;
            unsigned long long axy[SR], azw[SR];
#pragma unroll
            for (int r = 0; r < SR; r++) {
                float4 v = bp[r * (SCHUNK / 4) + d4l];
                axy[r] = pack2(v.x, v.y) & ABS2;
                azw[r] = pack2(v.z, v.w) & ABS2;
            }
            const int dg = c * SCHUNK + 4 * d4l;
#pragma unroll
            for (int h = 0; h < H_; h++) {
                const ulonglong2 wv = *(const ulonglong2*)&Wt[h * D_ + dg];
#pragma unroll
                for (int r = 0; r < SR; r++) {
                    FMA2(acc[r * 8 + h], axy[r], wv.x);
                    FMA2(acc[r * 8 + h], azw[r], wv.y);
                }
            }
        }

        if (c == 3) {
            int n = 32;
#pragma unroll
            for (int off = 16; off >= 1; off >>= 1) {
#pragma unroll
                for (int i = 0; i < 16; i++) {
                    if (i < n / 2) {
                        unsigned long long xx = acc[2 * i], yy = acc[2 * i + 1];
                        unsigned long long t = (lane & off) ? xx : yy;
                        t = shfl_xor64(t, off);
                        unsigned long long keep = (lane & off) ? yy : xx;
                        ADD2(keep, t);
                        acc[i] = keep;
                    }
                }
                n >>= 1;
            }
            const int row = batch * SR + rA;
            float lo, hi;
            unpack2(acc[0], lo, hi);
            float s = lo + hi + bias_h;
            const int b = row / F_;
            const int f = row - b * F_;
            const unsigned int finv = 0xFFFFFFFFu - (unsigned int)f;
            g_keys[(size_t)row * H_ + h0] =
                ((unsigned long long)f2ord(s) << 32) | (unsigned long long)finv;
        }
    }
}

// ---------------------------------------------------------------------------
// Kernel 2: per (b,h) exact radix-select with EARLY EXIT: once the selected
// bin holds a single key, that key IS the k-th largest -- find it and stop
// (expected after ~2-3 of 8 passes). Writes mask scratch in [bh][f] layout.
// ---------------------------------------------------------------------------
__global__ void __launch_bounds__(1024) topk_kernel(
    const float* __restrict__ sparsity_offset)
{
    __shared__ unsigned long long s[F_];   // 32 KB
    __shared__ int hist[4][256];
    __shared__ int sh_bin, sh_need, sh_c;
    __shared__ unsigned long long sh_thr;

    const int bh = blockIdx.x;
    const int b  = bh >> 3;
    const int h  = bh & (H_ - 1);
    const int t  = threadIdx.x;
    const int lane = t & 31;
    const int wg4 = (t >> 5) & 3;

#pragma unroll
    for (int j = 0; j < 4; j++) {
        int i = t + j * 1024;
        s[i] = g_keys[((size_t)b * F_ + i) * H_ + h];
    }

    if (t == 0) {
        double off = (double)sparsity_offset[h];
        double sp  = 1.0 / (1.0 + exp(-off)) * 0.3 + 0.15;
        int k = (int)((double)F_ * sp);     // trunc, matches numpy int()
        if (k < 1)  k = 1;
        if (k > F_) k = F_;
        sh_need = k;
    }
    __syncthreads();

    unsigned long long prefix = 0ull, pmask = 0ull;

    for (int shift = 56; shift >= 0; shift -= 8) {
        if (t < 256) { hist[0][t] = 0; hist[1][t] = 0; hist[2][t] = 0; hist[3][t] = 0; }
        __syncthreads();
#pragma unroll
        for (int j = 0; j < 4; j++) {
            unsigned long long key = s[t + j * 1024];
            if ((key & pmask) == prefix)
                atomicAdd(&hist[wg4][(int)((key >> shift) & 255ull)], 1);
        }
        __syncthreads();

        if (t < 32) {
            int c[8], lsum = 0;
#pragma unroll
            for (int q = 0; q < 8; q++) {
                int bin = lane * 8 + q;
                c[q] = hist[0][bin] + hist[1][bin] + hist[2][bin] + hist[3][bin];
                lsum += c[q];
            }
            int ssum = lsum;
#pragma unroll
            for (int off = 1; off < 32; off <<= 1) {
                int o = __shfl_down_sync(0xffffffffu, ssum, off);
                if (lane + off < 32) ssum += o;
            }
            int above = ssum - lsum;
            int need = sh_need;
            int cum = above;
#pragma unroll
            for (int q = 7; q >= 0; q--) {
                int bin = lane * 8 + q;
                if (cum < need && need <= cum + c[q]) {
                    sh_bin = bin;
                    sh_need = need - cum;
                    sh_c = c[q];
                }
                cum += c[q];
            }
        }
        __syncthreads();
        prefix |= ((unsigned long long)sh_bin) << shift;
        pmask  |= (255ull << shift);

        if (sh_c == 1) {
            // the unique key with this prefix is the k-th largest
#pragma unroll
            for (int j = 0; j < 4; j++) {
                unsigned long long key = s[t + j * 1024];
                if ((key & pmask) == prefix) sh_thr = key;
            }
            __syncthreads();
            break;
        }
        __syncthreads();
    }

    const unsigned long long thr = sh_thr;   // exact k-th largest key
    // mask scratch: keys distinct -> exactly k ones
#pragma unroll
    for (int j = 0; j < 4; j++) {
        int i = t + j * 1024;
        g_mask[(size_t)bh * F_ + i] = (s[i] >= thr) ? 1.0f : 0.0f;
    }
}

// ---------------------------------------------------------------------------
// Kernel 3: dense filter, ballot-partitioned. Per warp: bits = kept-rows
// bitmap; kept rows copied in batches of 4 (pure batched ldcs/stcs, MLP=4);
// zero rows are pure stores. Mask output folded in.
// ---------------------------------------------------------------------------
__global__ void __launch_bounds__(256) filter_kernel(
    const float* __restrict__ x,
    float* __restrict__ xout,
    float* __restrict__ mask_out)     // may be null
{
    __shared__ float m[TILE_][H_];
    const int tile0 = blockIdx.x * TILE_;
    const int b = tile0 >> 12;                    // F_ = 4096
    const int f0 = tile0 & (F_ - 1);
    const int t = threadIdx.x;
    const int head = t >> 5;
    const int lane = t & 31;

    // load mask tile from scratch (each warp loads its head's 32 floats)
    m[lane][head] = g_mask[((size_t)(b * H_ + head)) * F_ + f0 + lane];
    __syncthreads();

    if (mask_out)   // coalesced 2KB: row = t>>3, head = t&7
        mask_out[(size_t)tile0 * H_ + t] = m[t >> 3][t & 7];

    const bool kept = (m[lane][head] != 0.0f);    // lane indexes row
    const unsigned bits = __ballot_sync(0xffffffffu, kept);

    const size_t base = (size_t)tile0 * D_ + head * 128 + lane * 4;

    // kept rows: batches of 4 independent load+store
    unsigned kb = bits;
    while (kb) {
        int r0 = -1, r1 = -1, r2 = -1, r3 = -1;
        r0 = __ffs(kb) - 1; kb &= kb - 1;
        if (kb) { r1 = __ffs(kb) - 1; kb &= kb - 1; }
        if (kb) { r2 = __ffs(kb) - 1; kb &= kb - 1; }
        if (kb) { r3 = __ffs(kb) - 1; kb &= kb - 1; }
        float4 v0, v1, v2, v3;
        v0 = __ldcs((const float4*)(x + base + (size_t)r0 * D_));
        if (r1 >= 0) v1 = __ldcs((const float4*)(x + base + (size_t)r1 * D_));
        if (r2 >= 0) v2 = __ldcs((const float4*)(x + base + (size_t)r2 * D_));
        if (r3 >= 0) v3 = __ldcs((const float4*)(x + base + (size_t)r3 * D_));
        __stcs((float4*)(xout + base + (size_t)r0 * D_), v0);
        if (r1 >= 0) __stcs((float4*)(xout + base + (size_t)r1 * D_), v1);
        if (r2 >= 0) __stcs((float4*)(xout + base + (size_t)r2 * D_), v2);
        if (r3 >= 0) __stcs((float4*)(xout + base + (size_t)r3 * D_), v3);
    }

    // zero rows: pure stores
    const float4 z4 = make_float4(0.f, 0.f, 0.f, 0.f);
    unsigned zb = ~bits;
    while (zb) {
        int r0 = __ffs(zb) - 1; zb &= zb - 1;
        __stcs((float4*)(xout + base + (size_t)r0 * D_), z4);
    }
}

// ---------------------------------------------------------------------------
extern "C" void kernel_launch(void* const* d_in, const int* in_sizes, int n_in,
                              void* d_out, int out_size)
{
    const float* x    = (const float*)d_in[0];  // (B,F,D)
    const float* W    = (const float*)d_in[1];  // (D,H)
    const float* bias = (const float*)d_in[2];  // (H)
    const float* soff = (const float*)d_in[3];  // (H)

    const int nrows = in_sizes[0] / D_;         // B*F
    const int B = nrows / F_;

    float* xout = (float*)d_out;
    float* mask_out = nullptr;
    long long need = (long long)nrows * D_ + (long long)nrows * H_;
    if ((long long)out_size >= need)
        mask_out = (float*)d_out + (size_t)nrows * D_;

    const int smem_bytes = (H_ * D_ + 8 * NSTG * STG_FLOATS) * sizeof(float); // 224KB
    static int attr_set = 0;
    if (!attr_set) {
        cudaFuncSetAttribute(score_kernel,
                             cudaFuncAttributeMaxDynamicSharedMemorySize, smem_bytes);
        attr_set = 1;
    }

    // 1) scores -> keys (round-11 pipeline, measured 28.7us)
    score_kernel<<<148, 256, smem_bytes>>>(x, W, bias, nrows);
    // 2) exact top-k with early-exit radix + mask scratch
    topk_kernel<<<B * H_, 1024>>>(soff);
    // 3) dense filter, ballot-partitioned, mask folded in
    filter_kernel<<<nrows / TILE_, 256>>>(x, xout, mask_out);
}